// round 12
// baseline (speedup 1.0000x reference)
#include <cuda_runtime.h>
#include <cstdint>

#define N_   128
#define C_   64
#define CO_  64
#define T_   256
#define V_   25
#define R_   8
#define TV_  (T_ * V_)    // 6400
#define ADJP 28

// scratch (device globals -- no allocation allowed)
__device__ float g_xm[N_ * C_ * V_];                    // [n][c][v]
__device__ float g_adj[N_ * CO_ * V_ * ADJP];           // [n][o][u][28]
__device__ float g_x3[(size_t)N_ * CO_ * TV_];          // [n][o][tv]  ~210MB

typedef unsigned long long u64;

__device__ __forceinline__ u64 fma2(u64 a, u64 b, u64 c) {
    u64 d; asm("fma.rn.f32x2 %0, %1, %2, %3;" : "=l"(d) : "l"(a), "l"(b), "l"(c)); return d;
}
__device__ __forceinline__ u64 pack2(float lo, float hi) {
    u64 r; asm("mov.b64 %0, {%1,%2};" : "=l"(r) : "f"(lo), "f"(hi)); return r;
}
__device__ __forceinline__ void unpack2(u64 v, float& lo, float& hi) {
    asm("mov.b64 {%0,%1}, %2;" : "=f"(lo), "=f"(hi) : "l"(v));
}
__device__ __forceinline__ uint32_t f2tf32(float f) {
    uint32_t u; asm("cvt.rna.tf32.f32 %0, %1;" : "=r"(u) : "f"(f)); return u;
}
__device__ __forceinline__ void mma_tf32(float c[4], const uint32_t a[4],
                                         uint32_t b0, uint32_t b1) {
    asm volatile(
        "mma.sync.aligned.m16n8k8.row.col.f32.tf32.tf32.f32 "
        "{%0,%1,%2,%3}, {%4,%5,%6,%7}, {%8,%9}, {%0,%1,%2,%3};"
        : "+f"(c[0]), "+f"(c[1]), "+f"(c[2]), "+f"(c[3])
        : "r"(a[0]), "r"(a[1]), "r"(a[2]), "r"(a[3]), "r"(b0), "r"(b1));
}
__device__ __forceinline__ uint32_t smem_u32(const void* p) {
    uint32_t a;
    asm("{ .reg .u64 t; cvta.to.shared.u64 t, %1; cvt.u32.u64 %0, t; }" : "=r"(a) : "l"(p));
    return a;
}
#define CP_ASYNC16(dst, src) \
    asm volatile("cp.async.ca.shared.global [%0], [%1], 16;" :: "r"(dst), "l"(src))
#define CP_COMMIT() asm volatile("cp.async.commit_group;" ::: "memory")
#define CP_WAIT(n)  asm volatile("cp.async.wait_group %0;" :: "n"(n) : "memory")

// k3a smem layout (uint32 words)
#define SA_PITCH 136
#define SB_PITCH 72
#define ST_PITCH 132                        // stage [o][tv] pitch
#define SA_WORDS (64 * SA_PITCH)            // 8704 per buffer (>= stage 64*132=8448)
#define SB_WORDS (64 * SB_PITCH)            // 4608
#define K3A_WORDS (2 * SA_WORDS + 2 * SB_WORDS + 64)
#define K3A_SMEM  (K3A_WORDS * 4)           // 106,752 B

// ---------------------------------------------------------------------------
// Kernel 1: xm[n,c,v] = sum_t x[n,c,t,v]
// ---------------------------------------------------------------------------
__global__ void k1_tsum(const float* __restrict__ x) {
    __shared__ float tile[TV_];
    __shared__ float part[8][V_];
    const int bx  = blockIdx.x;               // n*64 + c
    const int tid = threadIdx.x;

    const float4* src = reinterpret_cast<const float4*>(x + (size_t)bx * TV_);
    float4* dst = reinterpret_cast<float4*>(tile);
    for (int i = tid; i < TV_ / 4; i += 256) dst[i] = src[i];
    __syncthreads();

    if (tid < 200) {
        const int g = tid / 25, v = tid - g * 25;
        float s = 0.f;
        const int tb = g * 32;
        #pragma unroll 8
        for (int t = tb; t < tb + 32; ++t) s += tile[t * V_ + v];
        part[g][v] = s;
    }
    __syncthreads();

    if (tid < V_) {
        float s = 0.f;
        #pragma unroll
        for (int g = 0; g < 8; ++g) s += part[g][tid];
        g_xm[bx * V_ + tid] = s;
    }
}

// ---------------------------------------------------------------------------
// Kernel 2: adj[n,o,u,v] = sum_r W4[o,r]*tanh(x1[u]-x2[v]) + b4[o] + A[u,v]
// ---------------------------------------------------------------------------
__global__ void k2_adj(const float* __restrict__ A,
                       const float* __restrict__ W1, const float* __restrict__ b1,
                       const float* __restrict__ W2, const float* __restrict__ b2,
                       const float* __restrict__ W4, const float* __restrict__ b4) {
    __shared__ float sxm[C_ * V_];
    __shared__ float sx1[R_ * V_];
    __shared__ float sx2[R_ * V_];
    __shared__ float sW4[CO_ * R_];
    __shared__ float sA[V_ * V_];
    __shared__ float sb4[CO_];

    const int n = blockIdx.x, tid = threadIdx.x;
    for (int i = tid; i < C_ * V_;  i += 256) sxm[i] = g_xm[n * C_ * V_ + i];
    for (int i = tid; i < CO_ * R_; i += 256) sW4[i] = W4[i];
    for (int i = tid; i < V_ * V_;  i += 256) sA[i]  = A[i];
    if (tid < CO_) sb4[tid] = b4[tid];
    __syncthreads();

    if (tid < R_ * V_) {
        const int r = tid / V_, v = tid - r * V_;
        float s1 = 0.f, s2 = 0.f;
        for (int c = 0; c < C_; ++c) {
            const float xv = sxm[c * V_ + v];
            s1 = fmaf(W1[r * C_ + c], xv, s1);
            s2 = fmaf(W2[r * C_ + c], xv, s2);
        }
        sx1[tid] = s1 * (1.0f / T_) + b1[r];
        sx2[tid] = s2 * (1.0f / T_) + b2[r];
    }
    __syncthreads();

    for (int p = tid; p < V_ * V_; p += 256) {
        const int u = p / V_, v = p - u * V_;
        float y[R_];
        #pragma unroll
        for (int r = 0; r < R_; ++r) y[r] = tanhf(sx1[r * V_ + u] - sx2[r * V_ + v]);
        const float av = sA[p];
        float* out = &g_adj[((size_t)(n * CO_) * V_ + u) * ADJP + v];
        for (int o = 0; o < CO_; ++o) {
            float s = sb4[o];
            #pragma unroll
            for (int r = 0; r < R_; ++r) s = fmaf(sW4[o * R_ + r], y[r], s);
            out[(size_t)o * V_ * ADJP] = s + av;
        }
    }

    if (tid < 75) {
        const int u = tid / 3, pv = 25 + (tid - (tid / 3) * 3);
        for (int o = 0; o < CO_; ++o)
            g_adj[((size_t)(n * CO_ + o) * V_ + u) * ADJP + pv] = 0.f;
    }
}

// ---------------------------------------------------------------------------
// Kernel 3a (HMMA tf32, cp.async double-buffered, transposed stage):
//   x3[n,o,tv] = b3[o] + sum_c W3[o,c] x[n,c,tv]
// ---------------------------------------------------------------------------
__global__ void __launch_bounds__(256, 2)
k3a_hmma(const float* __restrict__ x, const float* __restrict__ W3,
         const float* __restrict__ b3) {
    extern __shared__ uint32_t smw[];
    uint32_t* sBh = smw + 2 * SA_WORDS;
    uint32_t* sBl = sBh + SB_WORDS;
    float*    sb3 = reinterpret_cast<float*>(sBl + SB_WORDS);
    const uint32_t sA_addr = smem_u32(smw);

    const int tid  = threadIdx.x;
    const int wid  = tid >> 5;
    const int lane = tid & 31;
    const int lc   = lane & 3;
    const int lg   = lane >> 2;
    const int wm   = wid & 3;       // tv group (32 rows)
    const int wn   = wid >> 2;      // o half (32 cols)

    const int blk   = blockIdx.x;   // n*10 + chunk
    const int n     = blk / 10;
    const int chunk = blk - n * 10;

    for (int i = tid; i < 4096; i += 256) {
        const int o = i >> 6, c = i & 63;
        const float w = W3[i];
        const uint32_t hb = f2tf32(w);
        const uint32_t lb = f2tf32(w - __uint_as_float(hb));
        sBh[c * SB_PITCH + o] = hb;
        sBl[c * SB_PITCH + o] = lb;
    }
    if (tid < 64) sb3[tid] = b3[tid];

    const float* xg = x + (size_t)n * C_ * TV_;

    auto fill = [&](int b, int tv0) {
        const uint32_t dbase = sA_addr + (uint32_t)(b * SA_WORDS) * 4;
        #pragma unroll
        for (int r = 0; r < 8; ++r) {
            const int i = tid + 256 * r;          // 2048 16B chunks
            const int c = i >> 5, j = i & 31;
            CP_ASYNC16(dbase + (uint32_t)(c * SA_PITCH + j * 4) * 4,
                       xg + (size_t)c * TV_ + tv0 + j * 4);
        }
    };

    fill(0, (chunk * 5) * 128);
    CP_COMMIT();

    for (int tile = 0; tile < 5; ++tile) {
        if (tile < 4) {
            fill((tile + 1) & 1, (chunk * 5 + tile + 1) * 128);
            CP_COMMIT();
            CP_WAIT(1);
        } else {
            CP_WAIT(0);
        }
        __syncthreads();

        uint32_t* sA = smw + (tile & 1) * SA_WORDS;
        const int tv0 = (chunk * 5 + tile) * 128;

        float acc[2][4][4];
        #pragma unroll
        for (int mt = 0; mt < 2; ++mt)
            #pragma unroll
            for (int nt = 0; nt < 4; ++nt)
                #pragma unroll
                for (int j = 0; j < 4; ++j) acc[mt][nt][j] = 0.f;

        #pragma unroll
        for (int k0 = 0; k0 < 64; k0 += 8) {
            uint32_t a[2][4];
            #pragma unroll
            for (int mt = 0; mt < 2; ++mt) {
                const int base = (k0 + lc) * SA_PITCH + wm * 32 + mt * 16 + lg;
                a[mt][0] = sA[base];
                a[mt][1] = sA[base + 8];
                a[mt][2] = sA[base + 4 * SA_PITCH];
                a[mt][3] = sA[base + 8 + 4 * SA_PITCH];
            }
            #pragma unroll
            for (int nt = 0; nt < 4; ++nt) {
                const int bbase = (k0 + lc) * SB_PITCH + wn * 32 + nt * 8 + lg;
                const uint32_t bh0 = sBh[bbase], bh1 = sBh[bbase + 4 * SB_PITCH];
                const uint32_t bl0 = sBl[bbase], bl1 = sBl[bbase + 4 * SB_PITCH];
                mma_tf32(acc[0][nt], a[0], bh0, bh1);
                mma_tf32(acc[0][nt], a[0], bl0, bl1);
                mma_tf32(acc[1][nt], a[1], bh0, bh1);
                mma_tf32(acc[1][nt], a[1], bl0, bl1);
            }
        }
        __syncthreads();   // frag reads done; reuse this A buffer as stage

        // transposed stage: stageT[o][tv] pitch 132 (conflict-free STS + LDS)
        float* stageT = reinterpret_cast<float*>(sA);
        #pragma unroll
        for (int mt = 0; mt < 2; ++mt) {
            const int row = wm * 32 + mt * 16 + lg;
            #pragma unroll
            for (int nt = 0; nt < 4; ++nt) {
                const int col = wn * 32 + nt * 8 + 2 * lc;
                const float b0v = sb3[col], b1v = sb3[col + 1];
                stageT[col * ST_PITCH + row]             = acc[mt][nt][0] + b0v;
                stageT[(col + 1) * ST_PITCH + row]       = acc[mt][nt][1] + b1v;
                stageT[col * ST_PITCH + row + 8]         = acc[mt][nt][2] + b0v;
                stageT[(col + 1) * ST_PITCH + row + 8]   = acc[mt][nt][3] + b1v;
            }
        }
        __syncthreads();

        #pragma unroll
        for (int r = 0; r < 8; ++r) {
            const int o = wid * 8 + r;
            const float4 v = *reinterpret_cast<const float4*>(&stageT[o * ST_PITCH + 4 * lane]);
            *reinterpret_cast<float4*>(g_x3 + (size_t)(n * CO_ + o) * TV_ + tv0 + 4 * lane) = v;
        }
        __syncthreads();
    }
}

// ---------------------------------------------------------------------------
// Kernel 3b: per block (n,o):  z[t,u] = sum_v adj[u,v] * x3[t,v]
//   adj + x-row loads as LDS.128 (7 float4 per row) -> L1 wavefronts halved.
// ---------------------------------------------------------------------------
__global__ void __launch_bounds__(256, 5)
k3b_apply(float* __restrict__ z) {
    __shared__ float sadj[V_ * ADJP];        // [u][28], pads zero (from k2)
    __shared__ float sbuf[T_ * ADJP];        // [t][28] x3 tile -> flat z tile

    const int blk = blockIdx.x;       // n*64 + o
    const int tid = threadIdx.x;      // = t

    const float* asrc = g_adj + (size_t)blk * (V_ * ADJP);
    for (int i = tid; i < V_ * ADJP; i += 256) sadj[i] = asrc[i];

    const float4* xsrc = reinterpret_cast<const float4*>(g_x3 + (size_t)blk * TV_);
    for (int i = tid; i < TV_ / 4; i += 256) {
        const float4 f = xsrc[i];
        const int e = i * 4;
        float fv[4] = {f.x, f.y, f.z, f.w};
        #pragma unroll
        for (int k = 0; k < 4; ++k) {
            const int ee = e + k;
            const int t = ee / 25, v = ee - t * 25;
            sbuf[t * ADJP + v] = fv[k];
        }
    }
    // zero all 3 pad lanes of this thread's row (pad pair 13 must be exact 0)
    sbuf[tid * ADJP + 25] = 0.f;
    sbuf[tid * ADJP + 26] = 0.f;
    sbuf[tid * ADJP + 27] = 0.f;
    __syncthreads();

    // own x3 row: 7 LDS.128 -> 14 u64 pairs
    u64 xr2[14];
    {
        const float4* r4 = reinterpret_cast<const float4*>(&sbuf[tid * ADJP]);
        #pragma unroll
        for (int j = 0; j < 7; ++j) {
            const float4 q = r4[j];
            xr2[2 * j]     = pack2(q.x, q.y);
            xr2[2 * j + 1] = pack2(q.z, q.w);
        }
    }
    __syncthreads();   // rows captured; sbuf reusable as flat z stage

    float* zrow = &sbuf[tid * V_];
    #pragma unroll
    for (int u = 0; u < 25; ++u) {
        const float4* ar4 = reinterpret_cast<const float4*>(&sadj[u * ADJP]);
        u64 acc = 0ull;
        #pragma unroll
        for (int j = 0; j < 7; ++j) {
            const float4 q = ar4[j];                 // broadcast LDS.128
            acc = fma2(pack2(q.x, q.y), xr2[2 * j],     acc);
            acc = fma2(pack2(q.z, q.w), xr2[2 * j + 1], acc);
        }
        float lo, hi; unpack2(acc, lo, hi);
        zrow[u] = lo + hi;
    }
    __syncthreads();

    float4* zb = reinterpret_cast<float4*>(z + (size_t)blk * TV_);
    const float4* s4 = reinterpret_cast<const float4*>(sbuf);
    for (int i = tid; i < TV_ / 4; i += 256) zb[i] = s4[i];
}

// ---------------------------------------------------------------------------
extern "C" void kernel_launch(void* const* d_in, const int* in_sizes, int n_in,
                              void* d_out, int out_size) {
    (void)in_sizes; (void)n_in; (void)out_size;
    const float* x  = (const float*)d_in[0];
    const float* A  = (const float*)d_in[1];
    const float* W1 = (const float*)d_in[2];
    const float* b1 = (const float*)d_in[3];
    const float* W2 = (const float*)d_in[4];
    const float* b2 = (const float*)d_in[5];
    const float* W3 = (const float*)d_in[6];
    const float* b3 = (const float*)d_in[7];
    const float* W4 = (const float*)d_in[8];
    const float* b4 = (const float*)d_in[9];
    float* z = (float*)d_out;

    cudaFuncSetAttribute(k3a_hmma, cudaFuncAttributeMaxDynamicSharedMemorySize, K3A_SMEM);

    k1_tsum<<<N_ * C_, 256>>>(x);
    k2_adj<<<N_, 256>>>(A, W1, b1, W2, b2, W4, b4);
    k3a_hmma<<<N_ * 10, 256, K3A_SMEM>>>(x, W3, b3);
    k3b_apply<<<N_ * CO_, 256>>>(z);
}

// round 13
// speedup vs baseline: 1.0296x; 1.0296x over previous
#include <cuda_runtime.h>
#include <cstdint>

#define N_   128
#define C_   64
#define CO_  64
#define T_   256
#define V_   25
#define R_   8
#define TV_  (T_ * V_)    // 6400
#define ADJP 28
#define NCHUNK 10
#define CHUNK_TV 640

// scratch (device globals -- no allocation allowed)
__device__ float g_xmp[N_ * NCHUNK * C_ * V_];          // per-chunk partial t-sums
__device__ float g_adj[N_ * CO_ * V_ * ADJP];           // [n][o][u][28]
__device__ float g_x3[(size_t)N_ * CO_ * TV_];          // [n][o][tv]  ~210MB

typedef unsigned long long u64;

__device__ __forceinline__ u64 fma2(u64 a, u64 b, u64 c) {
    u64 d; asm("fma.rn.f32x2 %0, %1, %2, %3;" : "=l"(d) : "l"(a), "l"(b), "l"(c)); return d;
}
__device__ __forceinline__ void unpack2(u64 v, float& lo, float& hi) {
    asm("mov.b64 {%0,%1}, %2;" : "=f"(lo), "=f"(hi) : "l"(v));
}
__device__ __forceinline__ uint32_t f2tf32(float f) {
    uint32_t u; asm("cvt.rna.tf32.f32 %0, %1;" : "=r"(u) : "f"(f)); return u;
}
__device__ __forceinline__ void mma_tf32(float c[4], const uint32_t a[4],
                                         uint32_t b0, uint32_t b1) {
    asm volatile(
        "mma.sync.aligned.m16n8k8.row.col.f32.tf32.tf32.f32 "
        "{%0,%1,%2,%3}, {%4,%5,%6,%7}, {%8,%9}, {%0,%1,%2,%3};"
        : "+f"(c[0]), "+f"(c[1]), "+f"(c[2]), "+f"(c[3])
        : "r"(a[0]), "r"(a[1]), "r"(a[2]), "r"(a[3]), "r"(b0), "r"(b1));
}
__device__ __forceinline__ uint32_t smem_u32(const void* p) {
    uint32_t a;
    asm("{ .reg .u64 t; cvta.to.shared.u64 t, %1; cvt.u32.u64 %0, t; }" : "=r"(a) : "l"(p));
    return a;
}
#define CP_ASYNC16(dst, src) \
    asm volatile("cp.async.ca.shared.global [%0], [%1], 16;" :: "r"(dst), "l"(src))
#define CP_COMMIT() asm volatile("cp.async.commit_group;" ::: "memory")
#define CP_WAIT(n)  asm volatile("cp.async.wait_group %0;" :: "n"(n) : "memory")

// k3a smem layout (uint32 words)
#define SA_PITCH 136
#define SB_PITCH 72
#define ST_PITCH 132                        // stage [o][tv] pitch
#define SA_WORDS (64 * SA_PITCH)
#define SB_WORDS (64 * SB_PITCH)
#define K3A_WORDS (2 * SA_WORDS + 2 * SB_WORDS + 64)
#define K3A_SMEM  (K3A_WORDS * 4)           // 106,752 B

// ---------------------------------------------------------------------------
// Kernel 2: adj[n,o,u,v] = sum_r W4[o,r]*tanh(x1[u]-x2[v]) + b4[o] + A[u,v]
//   (reduces the 10 per-chunk xm partials written by k3a)
// ---------------------------------------------------------------------------
__global__ void k2_adj(const float* __restrict__ A,
                       const float* __restrict__ W1, const float* __restrict__ b1,
                       const float* __restrict__ W2, const float* __restrict__ b2,
                       const float* __restrict__ W4, const float* __restrict__ b4) {
    __shared__ float sxm[C_ * V_];
    __shared__ float sx1[R_ * V_];
    __shared__ float sx2[R_ * V_];
    __shared__ float sW4[CO_ * R_];
    __shared__ float sA[V_ * V_];
    __shared__ float sb4[CO_];

    const int n = blockIdx.x, tid = threadIdx.x;
    for (int i = tid; i < C_ * V_; i += 256) {
        float s = 0.f;
        #pragma unroll
        for (int ch = 0; ch < NCHUNK; ++ch)
            s += g_xmp[((size_t)n * NCHUNK + ch) * (C_ * V_) + i];
        sxm[i] = s;
    }
    for (int i = tid; i < CO_ * R_; i += 256) sW4[i] = W4[i];
    for (int i = tid; i < V_ * V_;  i += 256) sA[i]  = A[i];
    if (tid < CO_) sb4[tid] = b4[tid];
    __syncthreads();

    if (tid < R_ * V_) {
        const int r = tid / V_, v = tid - r * V_;
        float s1 = 0.f, s2 = 0.f;
        for (int c = 0; c < C_; ++c) {
            const float xv = sxm[c * V_ + v];
            s1 = fmaf(W1[r * C_ + c], xv, s1);
            s2 = fmaf(W2[r * C_ + c], xv, s2);
        }
        sx1[tid] = s1 * (1.0f / T_) + b1[r];
        sx2[tid] = s2 * (1.0f / T_) + b2[r];
    }
    __syncthreads();

    for (int p = tid; p < V_ * V_; p += 256) {
        const int u = p / V_, v = p - u * V_;
        float y[R_];
        #pragma unroll
        for (int r = 0; r < R_; ++r) y[r] = tanhf(sx1[r * V_ + u] - sx2[r * V_ + v]);
        const float av = sA[p];
        float* out = &g_adj[((size_t)(n * CO_) * V_ + u) * ADJP + v];
        for (int o = 0; o < CO_; ++o) {
            float s = sb4[o];
            #pragma unroll
            for (int r = 0; r < R_; ++r) s = fmaf(sW4[o * R_ + r], y[r], s);
            out[(size_t)o * V_ * ADJP] = s + av;
        }
    }

    if (tid < 75) {
        const int u = tid / 3, pv = 25 + (tid - (tid / 3) * 3);
        for (int o = 0; o < CO_; ++o)
            g_adj[((size_t)(n * CO_ + o) * V_ + u) * ADJP + pv] = 0.f;
    }
}

// ---------------------------------------------------------------------------
// Kernel 3a (HMMA tf32, cp.async double-buffered, fused xm partial sums):
//   x3[n,o,tv] = b3[o] + sum_c W3[o,c] x[n,c,tv]
//   + g_xmp[n][chunk][c][v] = sum over this chunk's t of x[n,c,t,v]
// ---------------------------------------------------------------------------
__global__ void __launch_bounds__(256, 2)
k3a_hmma(const float* __restrict__ x, const float* __restrict__ W3,
         const float* __restrict__ b3) {
    extern __shared__ uint32_t smw[];
    uint32_t* sBh = smw + 2 * SA_WORDS;
    uint32_t* sBl = sBh + SB_WORDS;
    float*    sb3 = reinterpret_cast<float*>(sBl + SB_WORDS);
    const uint32_t sA_addr = smem_u32(smw);

    const int tid  = threadIdx.x;
    const int wid  = tid >> 5;
    const int lane = tid & 31;
    const int lc   = lane & 3;
    const int lg   = lane >> 2;
    const int wm   = wid & 3;       // tv group (32 rows)
    const int wn   = wid >> 2;      // o half (32 cols)

    const int blk   = blockIdx.x;   // n*10 + chunk
    const int n     = blk / 10;
    const int chunk = blk - n * 10;

    for (int i = tid; i < 4096; i += 256) {
        const int o = i >> 6, c = i & 63;
        const float w = W3[i];
        const uint32_t hb = f2tf32(w);
        const uint32_t lb = f2tf32(w - __uint_as_float(hb));
        sBh[c * SB_PITCH + o] = hb;
        sBl[c * SB_PITCH + o] = lb;
    }
    if (tid < 64) sb3[tid] = b3[tid];

    const float* xg = x + (size_t)n * C_ * TV_;

    auto fill = [&](int b, int tv0) {
        const uint32_t dbase = sA_addr + (uint32_t)(b * SA_WORDS) * 4;
        #pragma unroll
        for (int r = 0; r < 8; ++r) {
            const int i = tid + 256 * r;          // 2048 16B chunks
            const int c = i >> 5, j = i & 31;
            CP_ASYNC16(dbase + (uint32_t)(c * SA_PITCH + j * 4) * 4,
                       xg + (size_t)c * TV_ + tv0 + j * 4);
        }
    };

    // xm partial accumulators: keys kk = tid + 256*slot, kk = c*25+v
    float xmacc[7];
    #pragma unroll
    for (int s = 0; s < 7; ++s) xmacc[s] = 0.f;

    fill(0, (chunk * 5) * 128);
    CP_COMMIT();

    for (int tile = 0; tile < 5; ++tile) {
        if (tile < 4) {
            fill((tile + 1) & 1, (chunk * 5 + tile + 1) * 128);
            CP_COMMIT();
            CP_WAIT(1);
        } else {
            CP_WAIT(0);
        }
        __syncthreads();

        uint32_t* sA = smw + (tile & 1) * SA_WORDS;
        const int tv0 = (chunk * 5 + tile) * 128;

        // fused xm partial sums over this tile (deterministic order)
        {
            const int base = tv0 % 25;
            const float* sAf = reinterpret_cast<const float*>(sA);
            int slot = 0;
            for (int kk = tid; kk < C_ * V_; kk += 256, ++slot) {
                const int c = kk / 25, v = kk - (kk / 25) * 25;
                int tvl = v - base; if (tvl < 0) tvl += 25;
                float s = xmacc[slot];
                const float* row = sAf + c * SA_PITCH;
                #pragma unroll 2
                for (; tvl < 128; tvl += 25) s += row[tvl];
                xmacc[slot] = s;
            }
        }

        float acc[2][4][4];
        #pragma unroll
        for (int mt = 0; mt < 2; ++mt)
            #pragma unroll
            for (int nt = 0; nt < 4; ++nt)
                #pragma unroll
                for (int j = 0; j < 4; ++j) acc[mt][nt][j] = 0.f;

        #pragma unroll
        for (int k0 = 0; k0 < 64; k0 += 8) {
            uint32_t a[2][4];
            #pragma unroll
            for (int mt = 0; mt < 2; ++mt) {
                const int base = (k0 + lc) * SA_PITCH + wm * 32 + mt * 16 + lg;
                a[mt][0] = sA[base];
                a[mt][1] = sA[base + 8];
                a[mt][2] = sA[base + 4 * SA_PITCH];
                a[mt][3] = sA[base + 8 + 4 * SA_PITCH];
            }
            #pragma unroll
            for (int nt = 0; nt < 4; ++nt) {
                const int bbase = (k0 + lc) * SB_PITCH + wn * 32 + nt * 8 + lg;
                const uint32_t bh0 = sBh[bbase], bh1 = sBh[bbase + 4 * SB_PITCH];
                const uint32_t bl0 = sBl[bbase], bl1 = sBl[bbase + 4 * SB_PITCH];
                mma_tf32(acc[0][nt], a[0], bh0, bh1);
                mma_tf32(acc[0][nt], a[0], bl0, bl1);
                mma_tf32(acc[1][nt], a[1], bh0, bh1);
                mma_tf32(acc[1][nt], a[1], bl0, bl1);
            }
        }
        __syncthreads();   // frag + xm reads done; reuse this A buffer as stage

        float* stageT = reinterpret_cast<float*>(sA);   // [o][tv] pitch 132
        #pragma unroll
        for (int mt = 0; mt < 2; ++mt) {
            const int row = wm * 32 + mt * 16 + lg;
            #pragma unroll
            for (int nt = 0; nt < 4; ++nt) {
                const int col = wn * 32 + nt * 8 + 2 * lc;
                const float b0v = sb3[col], b1v = sb3[col + 1];
                stageT[col * ST_PITCH + row]             = acc[mt][nt][0] + b0v;
                stageT[(col + 1) * ST_PITCH + row]       = acc[mt][nt][1] + b1v;
                stageT[col * ST_PITCH + row + 8]         = acc[mt][nt][2] + b0v;
                stageT[(col + 1) * ST_PITCH + row + 8]   = acc[mt][nt][3] + b1v;
            }
        }
        __syncthreads();

        #pragma unroll
        for (int r = 0; r < 8; ++r) {
            const int o = wid * 8 + r;
            const float4 v = *reinterpret_cast<const float4*>(&stageT[o * ST_PITCH + 4 * lane]);
            *reinterpret_cast<float4*>(g_x3 + (size_t)(n * CO_ + o) * TV_ + tv0 + 4 * lane) = v;
        }
        __syncthreads();
    }

    // write per-chunk xm partials
    {
        float* dst = g_xmp + ((size_t)n * NCHUNK + chunk) * (C_ * V_);
        int slot = 0;
        for (int kk = tid; kk < C_ * V_; kk += 256, ++slot) dst[kk] = xmacc[slot];
    }
}

// ---------------------------------------------------------------------------
// Kernel 3b (round-11 proven version): per block (n,o):
//   z[t,u] = sum_v adj[u,v] * x3[t,v]   via 13 f32x2 pairs per u.
// ---------------------------------------------------------------------------
__global__ void __launch_bounds__(256, 5)
k3b_apply(float* __restrict__ z) {
    __shared__ float sadj[V_ * ADJP];        // [u][28], pads zero
    __shared__ float sbuf[T_ * ADJP];        // [t][28] x3 tile -> flat z tile

    const int blk = blockIdx.x;       // n*64 + o
    const int tid = threadIdx.x;      // = t

    const float* asrc = g_adj + (size_t)blk * (V_ * ADJP);
    for (int i = tid; i < V_ * ADJP; i += 256) sadj[i] = asrc[i];

    const float4* xsrc = reinterpret_cast<const float4*>(g_x3 + (size_t)blk * TV_);
    for (int i = tid; i < TV_ / 4; i += 256) {
        const float4 f = xsrc[i];
        const int e = i * 4;
        float fv[4] = {f.x, f.y, f.z, f.w};
        #pragma unroll
        for (int k = 0; k < 4; ++k) {
            const int ee = e + k;
            const int t = ee / 25, v = ee - t * 25;
            sbuf[t * ADJP + v] = fv[k];
        }
    }
    sbuf[tid * ADJP + 25] = 0.f;
    __syncthreads();

    u64 xr2[13];
    {
        const u64* r2 = reinterpret_cast<const u64*>(&sbuf[tid * ADJP]);
        #pragma unroll
        for (int j = 0; j < 13; ++j) xr2[j] = r2[j];
    }
    __syncthreads();

    float* zrow = &sbuf[tid * V_];
    #pragma unroll
    for (int u = 0; u < 25; ++u) {
        const u64* ar = reinterpret_cast<const u64*>(&sadj[u * ADJP]);
        u64 acc = 0ull;
        #pragma unroll
        for (int j = 0; j < 13; ++j) acc = fma2(ar[j], xr2[j], acc);
        float lo, hi; unpack2(acc, lo, hi);
        zrow[u] = lo + hi;
    }
    __syncthreads();

    float4* zb = reinterpret_cast<float4*>(z + (size_t)blk * TV_);
    const float4* s4 = reinterpret_cast<const float4*>(sbuf);
    for (int i = tid; i < TV_ / 4; i += 256) zb[i] = s4[i];
}

// ---------------------------------------------------------------------------
extern "C" void kernel_launch(void* const* d_in, const int* in_sizes, int n_in,
                              void* d_out, int out_size) {
    (void)in_sizes; (void)n_in; (void)out_size;
    const float* x  = (const float*)d_in[0];
    const float* A  = (const float*)d_in[1];
    const float* W1 = (const float*)d_in[2];
    const float* b1 = (const float*)d_in[3];
    const float* W2 = (const float*)d_in[4];
    const float* b2 = (const float*)d_in[5];
    const float* W3 = (const float*)d_in[6];
    const float* b3 = (const float*)d_in[7];
    const float* W4 = (const float*)d_in[8];
    const float* b4 = (const float*)d_in[9];
    float* z = (float*)d_out;

    cudaFuncSetAttribute(k3a_hmma, cudaFuncAttributeMaxDynamicSharedMemorySize, K3A_SMEM);

    k3a_hmma<<<N_ * 10, 256, K3A_SMEM>>>(x, W3, b3);   // also emits xm partials
    k2_adj<<<N_, 256>>>(A, W1, b1, W2, b2, W4, b4);
    k3b_apply<<<N_ * CO_, 256>>>(z);
}

// round 14
// speedup vs baseline: 1.0887x; 1.0573x over previous
#include <cuda_runtime.h>
#include <cstdint>

#define N_   128
#define C_   64
#define CO_  64
#define T_   256
#define V_   25
#define R_   8
#define TV_  (T_ * V_)    // 6400
#define ADJP 28
#define NCHUNK 10

// scratch (device globals -- no allocation allowed)
__device__ float g_xmp[N_ * NCHUNK * C_ * V_];          // per-chunk partial t-sums
__device__ float g_adj[N_ * CO_ * V_ * ADJP];           // [n][o][u][28]
__device__ float g_x3[(size_t)N_ * CO_ * TV_];          // [n][o][tv]  ~210MB

typedef unsigned long long u64;

__device__ __forceinline__ u64 fma2(u64 a, u64 b, u64 c) {
    u64 d; asm("fma.rn.f32x2 %0, %1, %2, %3;" : "=l"(d) : "l"(a), "l"(b), "l"(c)); return d;
}
__device__ __forceinline__ void unpack2(u64 v, float& lo, float& hi) {
    asm("mov.b64 {%0,%1}, %2;" : "=f"(lo), "=f"(hi) : "l"(v));
}
__device__ __forceinline__ uint32_t f2tf32(float f) {
    uint32_t u; asm("cvt.rna.tf32.f32 %0, %1;" : "=r"(u) : "f"(f)); return u;
}
__device__ __forceinline__ void mma_tf32(float c[4], const uint32_t a[4],
                                         uint32_t b0, uint32_t b1) {
    asm volatile(
        "mma.sync.aligned.m16n8k8.row.col.f32.tf32.tf32.f32 "
        "{%0,%1,%2,%3}, {%4,%5,%6,%7}, {%8,%9}, {%0,%1,%2,%3};"
        : "+f"(c[0]), "+f"(c[1]), "+f"(c[2]), "+f"(c[3])
        : "r"(a[0]), "r"(a[1]), "r"(a[2]), "r"(a[3]), "r"(b0), "r"(b1));
}
__device__ __forceinline__ uint32_t smem_u32(const void* p) {
    uint32_t a;
    asm("{ .reg .u64 t; cvta.to.shared.u64 t, %1; cvt.u32.u64 %0, t; }" : "=r"(a) : "l"(p));
    return a;
}
#define CP_ASYNC16(dst, src) \
    asm volatile("cp.async.ca.shared.global [%0], [%1], 16;" :: "r"(dst), "l"(src))
#define CP_COMMIT() asm volatile("cp.async.commit_group;" ::: "memory")
#define CP_WAIT(n)  asm volatile("cp.async.wait_group %0;" :: "n"(n) : "memory")

// k3a smem layout (uint32 words)
#define SA_PITCH 136
#define SB_PITCH 72
#define ST_PITCH 132                        // stage [o][tv] pitch
#define SA_WORDS (64 * SA_PITCH)
#define SB_WORDS (64 * SB_PITCH)
#define K3A_WORDS (2 * SA_WORDS + 2 * SB_WORDS + 64)
#define K3A_SMEM  (K3A_WORDS * 4)           // 106,752 B

// ---------------------------------------------------------------------------
// Kernel 2: adj[n,o,u,v] = sum_r W4[o,r]*tanh(x1[u]-x2[v]) + b4[o] + A[u,v]
//   (reduces the 10 per-chunk xm partials written by k3a)
// ---------------------------------------------------------------------------
__global__ void k2_adj(const float* __restrict__ A,
                       const float* __restrict__ W1, const float* __restrict__ b1,
                       const float* __restrict__ W2, const float* __restrict__ b2,
                       const float* __restrict__ W4, const float* __restrict__ b4) {
    __shared__ float sxm[C_ * V_];
    __shared__ float sx1[R_ * V_];
    __shared__ float sx2[R_ * V_];
    __shared__ float sW4[CO_ * R_];
    __shared__ float sA[V_ * V_];
    __shared__ float sb4[CO_];

    const int n = blockIdx.x, tid = threadIdx.x;
    for (int i = tid; i < C_ * V_; i += 256) {
        float s = 0.f;
        #pragma unroll
        for (int ch = 0; ch < NCHUNK; ++ch)
            s += g_xmp[((size_t)n * NCHUNK + ch) * (C_ * V_) + i];
        sxm[i] = s;
    }
    for (int i = tid; i < CO_ * R_; i += 256) sW4[i] = W4[i];
    for (int i = tid; i < V_ * V_;  i += 256) sA[i]  = A[i];
    if (tid < CO_) sb4[tid] = b4[tid];
    __syncthreads();

    if (tid < R_ * V_) {
        const int r = tid / V_, v = tid - r * V_;
        float s1 = 0.f, s2 = 0.f;
        for (int c = 0; c < C_; ++c) {
            const float xv = sxm[c * V_ + v];
            s1 = fmaf(W1[r * C_ + c], xv, s1);
            s2 = fmaf(W2[r * C_ + c], xv, s2);
        }
        sx1[tid] = s1 * (1.0f / T_) + b1[r];
        sx2[tid] = s2 * (1.0f / T_) + b2[r];
    }
    __syncthreads();

    for (int p = tid; p < V_ * V_; p += 256) {
        const int u = p / V_, v = p - u * V_;
        float y[R_];
        #pragma unroll
        for (int r = 0; r < R_; ++r) y[r] = tanhf(sx1[r * V_ + u] - sx2[r * V_ + v]);
        const float av = sA[p];
        float* out = &g_adj[((size_t)(n * CO_) * V_ + u) * ADJP + v];
        for (int o = 0; o < CO_; ++o) {
            float s = sb4[o];
            #pragma unroll
            for (int r = 0; r < R_; ++r) s = fmaf(sW4[o * R_ + r], y[r], s);
            out[(size_t)o * V_ * ADJP] = s + av;
        }
    }

    if (tid < 75) {
        const int u = tid / 3, pv = 25 + (tid - (tid / 3) * 3);
        for (int o = 0; o < CO_; ++o)
            g_adj[((size_t)(n * CO_ + o) * V_ + u) * ADJP + pv] = 0.f;
    }
}

// ---------------------------------------------------------------------------
// Kernel 3a (HMMA tf32, 512 threads, cp.async double-buffered, fused xm):
//   x3[n,o,tv] = b3[o] + sum_c W3[o,c] x[n,c,tv]
//   16 warps: wm = wid&7 (16-tv group), wn = wid>>3 (32-o half)
// ---------------------------------------------------------------------------
__global__ void __launch_bounds__(512, 2)
k3a_hmma(const float* __restrict__ x, const float* __restrict__ W3,
         const float* __restrict__ b3) {
    extern __shared__ uint32_t smw[];
    uint32_t* sBh = smw + 2 * SA_WORDS;
    uint32_t* sBl = sBh + SB_WORDS;
    float*    sb3 = reinterpret_cast<float*>(sBl + SB_WORDS);
    const uint32_t sA_addr = smem_u32(smw);

    const int tid  = threadIdx.x;
    const int wid  = tid >> 5;      // 0..15
    const int lane = tid & 31;
    const int lc   = lane & 3;
    const int lg   = lane >> 2;
    const int wm   = wid & 7;       // tv group (16 rows)
    const int wn   = wid >> 3;      // o half (32 cols)

    const int blk   = blockIdx.x;   // n*10 + chunk
    const int n     = blk / 10;
    const int chunk = blk - n * 10;

    for (int i = tid; i < 4096; i += 512) {
        const int o = i >> 6, c = i & 63;
        const float w = W3[i];
        const uint32_t hb = f2tf32(w);
        const uint32_t lb = f2tf32(w - __uint_as_float(hb));
        sBh[c * SB_PITCH + o] = hb;
        sBl[c * SB_PITCH + o] = lb;
    }
    if (tid < 64) sb3[tid] = b3[tid];

    const float* xg = x + (size_t)n * C_ * TV_;

    auto fill = [&](int b, int tv0) {
        const uint32_t dbase = sA_addr + (uint32_t)(b * SA_WORDS) * 4;
        #pragma unroll
        for (int r = 0; r < 4; ++r) {
            const int i = tid + 512 * r;          // 2048 16B chunks
            const int c = i >> 5, j = i & 31;
            CP_ASYNC16(dbase + (uint32_t)(c * SA_PITCH + j * 4) * 4,
                       xg + (size_t)c * TV_ + tv0 + j * 4);
        }
    };

    // xm partial accumulators: keys kk = tid + 512*slot (<= 4 slots)
    float xmacc[4];
    #pragma unroll
    for (int s = 0; s < 4; ++s) xmacc[s] = 0.f;

    fill(0, (chunk * 5) * 128);
    CP_COMMIT();

    for (int tile = 0; tile < 5; ++tile) {
        if (tile < 4) {
            fill((tile + 1) & 1, (chunk * 5 + tile + 1) * 128);
            CP_COMMIT();
            CP_WAIT(1);
        } else {
            CP_WAIT(0);
        }
        __syncthreads();

        uint32_t* sA = smw + (tile & 1) * SA_WORDS;
        const int tv0 = (chunk * 5 + tile) * 128;

        // fused xm partial sums over this tile
        {
            const int base = tv0 % 25;
            const float* sAf = reinterpret_cast<const float*>(sA);
            int slot = 0;
            for (int kk = tid; kk < C_ * V_; kk += 512, ++slot) {
                const int c = kk / 25, v = kk - (kk / 25) * 25;
                int tvl = v - base; if (tvl < 0) tvl += 25;
                float s = xmacc[slot];
                const float* row = sAf + c * SA_PITCH;
                #pragma unroll 2
                for (; tvl < 128; tvl += 25) s += row[tvl];
                xmacc[slot] = s;
            }
        }

        float acc[4][4];
        #pragma unroll
        for (int nt = 0; nt < 4; ++nt)
            #pragma unroll
            for (int j = 0; j < 4; ++j) acc[nt][j] = 0.f;

        #pragma unroll
        for (int k0 = 0; k0 < 64; k0 += 8) {
            uint32_t a[4];
            {
                const int base = (k0 + lc) * SA_PITCH + wm * 16 + lg;
                a[0] = sA[base];
                a[1] = sA[base + 8];
                a[2] = sA[base + 4 * SA_PITCH];
                a[3] = sA[base + 8 + 4 * SA_PITCH];
            }
            #pragma unroll
            for (int nt = 0; nt < 4; ++nt) {
                const int bbase = (k0 + lc) * SB_PITCH + wn * 32 + nt * 8 + lg;
                const uint32_t bh0 = sBh[bbase], bh1 = sBh[bbase + 4 * SB_PITCH];
                const uint32_t bl0 = sBl[bbase], bl1 = sBl[bbase + 4 * SB_PITCH];
                mma_tf32(acc[nt], a, bh0, bh1);
                mma_tf32(acc[nt], a, bl0, bl1);
            }
        }
        __syncthreads();   // frag + xm reads done; reuse this A buffer as stage

        float* stageT = reinterpret_cast<float*>(sA);   // [o][tv] pitch 132
        {
            const int row = wm * 16 + lg;
            #pragma unroll
            for (int nt = 0; nt < 4; ++nt) {
                const int col = wn * 32 + nt * 8 + 2 * lc;
                const float b0v = sb3[col], b1v = sb3[col + 1];
                stageT[col * ST_PITCH + row]             = acc[nt][0] + b0v;
                stageT[(col + 1) * ST_PITCH + row]       = acc[nt][1] + b1v;
                stageT[col * ST_PITCH + row + 8]         = acc[nt][2] + b0v;
                stageT[(col + 1) * ST_PITCH + row + 8]   = acc[nt][3] + b1v;
            }
        }
        __syncthreads();

        #pragma unroll
        for (int r = 0; r < 4; ++r) {
            const int o = wid * 4 + r;
            const float4 v = *reinterpret_cast<const float4*>(&stageT[o * ST_PITCH + 4 * lane]);
            *reinterpret_cast<float4*>(g_x3 + (size_t)(n * CO_ + o) * TV_ + tv0 + 4 * lane) = v;
        }
        __syncthreads();
    }

    // write per-chunk xm partials
    {
        float* dst = g_xmp + ((size_t)n * NCHUNK + chunk) * (C_ * V_);
        int slot = 0;
        for (int kk = tid; kk < C_ * V_; kk += 512, ++slot) dst[kk] = xmacc[slot];
    }
}

// ---------------------------------------------------------------------------
// Kernel 3b (round-11 proven version): per block (n,o):
//   z[t,u] = sum_v adj[u,v] * x3[t,v]   via 13 f32x2 pairs per u.
// ---------------------------------------------------------------------------
__global__ void __launch_bounds__(256, 5)
k3b_apply(float* __restrict__ z) {
    __shared__ float sadj[V_ * ADJP];        // [u][28], pads zero
    __shared__ float sbuf[T_ * ADJP];        // [t][28] x3 tile -> flat z tile

    const int blk = blockIdx.x;       // n*64 + o
    const int tid = threadIdx.x;      // = t

    const float* asrc = g_adj + (size_t)blk * (V_ * ADJP);
    for (int i = tid; i < V_ * ADJP; i += 256) sadj[i] = asrc[i];

    const float4* xsrc = reinterpret_cast<const float4*>(g_x3 + (size_t)blk * TV_);
    for (int i = tid; i < TV_ / 4; i += 256) {
        const float4 f = xsrc[i];
        const int e = i * 4;
        float fv[4] = {f.x, f.y, f.z, f.w};
        #pragma unroll
        for (int k = 0; k < 4; ++k) {
            const int ee = e + k;
            const int t = ee / 25, v = ee - t * 25;
            sbuf[t * ADJP + v] = fv[k];
        }
    }
    sbuf[tid * ADJP + 25] = 0.f;
    __syncthreads();

    u64 xr2[13];
    {
        const u64* r2 = reinterpret_cast<const u64*>(&sbuf[tid * ADJP]);
        #pragma unroll
        for (int j = 0; j < 13; ++j) xr2[j] = r2[j];
    }
    __syncthreads();

    float* zrow = &sbuf[tid * V_];
    #pragma unroll
    for (int u = 0; u < 25; ++u) {
        const u64* ar = reinterpret_cast<const u64*>(&sadj[u * ADJP]);
        u64 acc = 0ull;
        #pragma unroll
        for (int j = 0; j < 13; ++j) acc = fma2(ar[j], xr2[j], acc);
        float lo, hi; unpack2(acc, lo, hi);
        zrow[u] = lo + hi;
    }
    __syncthreads();

    float4* zb = reinterpret_cast<float4*>(z + (size_t)blk * TV_);
    const float4* s4 = reinterpret_cast<const float4*>(sbuf);
    for (int i = tid; i < TV_ / 4; i += 256) zb[i] = s4[i];
}

// ---------------------------------------------------------------------------
extern "C" void kernel_launch(void* const* d_in, const int* in_sizes, int n_in,
                              void* d_out, int out_size) {
    (void)in_sizes; (void)n_in; (void)out_size;
    const float* x  = (const float*)d_in[0];
    const float* A  = (const float*)d_in[1];
    const float* W1 = (const float*)d_in[2];
    const float* b1 = (const float*)d_in[3];
    const float* W2 = (const float*)d_in[4];
    const float* b2 = (const float*)d_in[5];
    const float* W3 = (const float*)d_in[6];
    const float* b3 = (const float*)d_in[7];
    const float* W4 = (const float*)d_in[8];
    const float* b4 = (const float*)d_in[9];
    float* z = (float*)d_out;

    cudaFuncSetAttribute(k3a_hmma, cudaFuncAttributeMaxDynamicSharedMemorySize, K3A_SMEM);

    k3a_hmma<<<N_ * 10, 512, K3A_SMEM>>>(x, W3, b3);   // also emits xm partials
    k2_adj<<<N_, 256>>>(A, W1, b1, W2, b2, W4, b4);
    k3b_apply<<<N_ * CO_, 256>>>(z);
}

// round 15
// speedup vs baseline: 1.1257x; 1.0340x over previous
#include <cuda_runtime.h>
#include <cstdint>

#define N_   128
#define C_   64
#define CO_  64
#define T_   256
#define V_   25
#define R_   8
#define TV_  (T_ * V_)    // 6400
#define ADJP 28
#define NCHUNK 10

// scratch (device globals -- no allocation allowed)
__device__ float g_xmp[N_ * NCHUNK * C_ * V_];          // per-chunk partial t-sums
__device__ float g_adj[N_ * CO_ * V_ * ADJP];           // [n][o][u][28]
__device__ float g_x3[(size_t)N_ * CO_ * TV_];          // [n][o][tv]  ~210MB

typedef unsigned long long u64;

__device__ __forceinline__ u64 fma2(u64 a, u64 b, u64 c) {
    u64 d; asm("fma.rn.f32x2 %0, %1, %2, %3;" : "=l"(d) : "l"(a), "l"(b), "l"(c)); return d;
}
__device__ __forceinline__ void unpack2(u64 v, float& lo, float& hi) {
    asm("mov.b64 {%0,%1}, %2;" : "=f"(lo), "=f"(hi) : "l"(v));
}
__device__ __forceinline__ uint32_t f2tf32(float f) {
    uint32_t u; asm("cvt.rna.tf32.f32 %0, %1;" : "=r"(u) : "f"(f)); return u;
}
__device__ __forceinline__ void mma_tf32(float c[4], const uint32_t a[4],
                                         uint32_t b0, uint32_t b1) {
    asm volatile(
        "mma.sync.aligned.m16n8k8.row.col.f32.tf32.tf32.f32 "
        "{%0,%1,%2,%3}, {%4,%5,%6,%7}, {%8,%9}, {%0,%1,%2,%3};"
        : "+f"(c[0]), "+f"(c[1]), "+f"(c[2]), "+f"(c[3])
        : "r"(a[0]), "r"(a[1]), "r"(a[2]), "r"(a[3]), "r"(b0), "r"(b1));
}
__device__ __forceinline__ uint32_t smem_u32(const void* p) {
    uint32_t a;
    asm("{ .reg .u64 t; cvta.to.shared.u64 t, %1; cvt.u32.u64 %0, t; }" : "=r"(a) : "l"(p));
    return a;
}
#define CP_ASYNC16(dst, src) \
    asm volatile("cp.async.ca.shared.global [%0], [%1], 16;" :: "r"(dst), "l"(src))
#define CP_COMMIT() asm volatile("cp.async.commit_group;" ::: "memory")
#define CP_WAIT(n)  asm volatile("cp.async.wait_group %0;" :: "n"(n) : "memory")

// k3a smem layout (uint32 words)
#define SA_PITCH 136
#define ST_PITCH 132                        // stage [o][tv] pitch
#define SA_WORDS (64 * SA_PITCH)            // 8704 per buffer
#define SBP_UINT4 2048                      // packed B: [wn][kb][nt][lane] uint4
#define K3A_WORDS (2 * SA_WORDS + 4 * SBP_UINT4 + 64)
#define K3A_SMEM  (K3A_WORDS * 4)           // 102,656 B

// ---------------------------------------------------------------------------
// Kernel 2: adj[n,o,u,v] = sum_r W4[o,r]*tanh(x1[u]-x2[v]) + b4[o] + A[u,v]
//   (reduces the 10 per-chunk xm partials written by k3a)
// ---------------------------------------------------------------------------
__global__ void k2_adj(const float* __restrict__ A,
                       const float* __restrict__ W1, const float* __restrict__ b1,
                       const float* __restrict__ W2, const float* __restrict__ b2,
                       const float* __restrict__ W4, const float* __restrict__ b4) {
    __shared__ float sxm[C_ * V_];
    __shared__ float sx1[R_ * V_];
    __shared__ float sx2[R_ * V_];
    __shared__ float sW4[CO_ * R_];
    __shared__ float sA[V_ * V_];
    __shared__ float sb4[CO_];

    const int n = blockIdx.x, tid = threadIdx.x;
    for (int i = tid; i < C_ * V_; i += 256) {
        float s = 0.f;
        #pragma unroll
        for (int ch = 0; ch < NCHUNK; ++ch)
            s += g_xmp[((size_t)n * NCHUNK + ch) * (C_ * V_) + i];
        sxm[i] = s;
    }
    for (int i = tid; i < CO_ * R_; i += 256) sW4[i] = W4[i];
    for (int i = tid; i < V_ * V_;  i += 256) sA[i]  = A[i];
    if (tid < CO_) sb4[tid] = b4[tid];
    __syncthreads();

    if (tid < R_ * V_) {
        const int r = tid / V_, v = tid - r * V_;
        float s1 = 0.f, s2 = 0.f;
        for (int c = 0; c < C_; ++c) {
            const float xv = sxm[c * V_ + v];
            s1 = fmaf(W1[r * C_ + c], xv, s1);
            s2 = fmaf(W2[r * C_ + c], xv, s2);
        }
        sx1[tid] = s1 * (1.0f / T_) + b1[r];
        sx2[tid] = s2 * (1.0f / T_) + b2[r];
    }
    __syncthreads();

    for (int p = tid; p < V_ * V_; p += 256) {
        const int u = p / V_, v = p - u * V_;
        float y[R_];
        #pragma unroll
        for (int r = 0; r < R_; ++r) y[r] = tanhf(sx1[r * V_ + u] - sx2[r * V_ + v]);
        const float av = sA[p];
        float* out = &g_adj[((size_t)(n * CO_) * V_ + u) * ADJP + v];
        for (int o = 0; o < CO_; ++o) {
            float s = sb4[o];
            #pragma unroll
            for (int r = 0; r < R_; ++r) s = fmaf(sW4[o * R_ + r], y[r], s);
            out[(size_t)o * V_ * ADJP] = s + av;
        }
    }

    if (tid < 75) {
        const int u = tid / 3, pv = 25 + (tid - (tid / 3) * 3);
        for (int o = 0; o < CO_; ++o)
            g_adj[((size_t)(n * CO_ + o) * V_ + u) * ADJP + pv] = 0.f;
    }
}

// ---------------------------------------------------------------------------
// Kernel 3a (HMMA tf32, 512 threads, packed B frags, fused xm):
//   x3[n,o,tv] = b3[o] + sum_c W3[o,c] x[n,c,tv]
// ---------------------------------------------------------------------------
__global__ void __launch_bounds__(512, 2)
k3a_hmma(const float* __restrict__ x, const float* __restrict__ W3,
         const float* __restrict__ b3) {
    extern __shared__ uint32_t smw[];
    uint4* sBp = reinterpret_cast<uint4*>(smw + 2 * SA_WORDS);   // 2048 uint4
    float* sb3 = reinterpret_cast<float*>(smw + 2 * SA_WORDS + 4 * SBP_UINT4);
    const uint32_t sA_addr = smem_u32(smw);

    const int tid  = threadIdx.x;
    const int wid  = tid >> 5;      // 0..15
    const int lane = tid & 31;
    const int lc   = lane & 3;
    const int lg   = lane >> 2;
    const int wm   = wid & 7;       // tv group (16 rows)
    const int wn   = wid >> 3;      // o half (32 cols)

    const int blk   = blockIdx.x;   // n*10 + chunk
    const int n     = blk / 10;
    const int chunk = blk - n * 10;

    // build packed B fragment table: sBp[((wnq*8 + kb)*4 + nt)*32 + ln]
    //   = {bh0, bh1, bl0, bl1} for (o = wnq*32+nt*8+lg', c0 = kb*8+lc', c1 = c0+4)
    #pragma unroll
    for (int r = 0; r < 4; ++r) {
        const int e = tid + 512 * r;          // 0..2047
        const int ln  = e & 31;
        const int nt  = (e >> 5) & 3;
        const int kb  = (e >> 7) & 7;
        const int wnq = e >> 10;
        const int lcq = ln & 3, lgq = ln >> 2;
        const int o  = wnq * 32 + nt * 8 + lgq;
        const int c0 = kb * 8 + lcq;
        const float w0 = W3[o * 64 + c0];
        const float w1 = W3[o * 64 + c0 + 4];
        const uint32_t h0 = f2tf32(w0), h1 = f2tf32(w1);
        const uint32_t l0 = f2tf32(w0 - __uint_as_float(h0));
        const uint32_t l1 = f2tf32(w1 - __uint_as_float(h1));
        sBp[e] = make_uint4(h0, h1, l0, l1);
    }
    if (tid < 64) sb3[tid] = b3[tid];

    const float* xg = x + (size_t)n * C_ * TV_;

    auto fill = [&](int b, int tv0) {
        const uint32_t dbase = sA_addr + (uint32_t)(b * SA_WORDS) * 4;
        #pragma unroll
        for (int r = 0; r < 4; ++r) {
            const int i = tid + 512 * r;          // 2048 16B chunks
            const int c = i >> 5, j = i & 31;
            CP_ASYNC16(dbase + (uint32_t)(c * SA_PITCH + j * 4) * 4,
                       xg + (size_t)c * TV_ + tv0 + j * 4);
        }
    };

    float xmacc[4];
    #pragma unroll
    for (int s = 0; s < 4; ++s) xmacc[s] = 0.f;

    fill(0, (chunk * 5) * 128);
    CP_COMMIT();

    for (int tile = 0; tile < 5; ++tile) {
        if (tile < 4) {
            fill((tile + 1) & 1, (chunk * 5 + tile + 1) * 128);
            CP_COMMIT();
            CP_WAIT(1);
        } else {
            CP_WAIT(0);
        }
        __syncthreads();

        uint32_t* sA = smw + (tile & 1) * SA_WORDS;
        const int tv0 = (chunk * 5 + tile) * 128;

        // fused xm partial sums over this tile
        {
            const int base = tv0 % 25;
            const float* sAf = reinterpret_cast<const float*>(sA);
            int slot = 0;
            for (int kk = tid; kk < C_ * V_; kk += 512, ++slot) {
                const int c = kk / 25, v = kk - (kk / 25) * 25;
                int tvl = v - base; if (tvl < 0) tvl += 25;
                float s = xmacc[slot];
                const float* row = sAf + c * SA_PITCH;
                #pragma unroll 2
                for (; tvl < 128; tvl += 25) s += row[tvl];
                xmacc[slot] = s;
            }
        }

        float acc[4][4];
        #pragma unroll
        for (int nt = 0; nt < 4; ++nt)
            #pragma unroll
            for (int j = 0; j < 4; ++j) acc[nt][j] = 0.f;

        const uint4* bp = sBp + (wn * 8) * 4 * 32 + lane;
        #pragma unroll
        for (int kb = 0; kb < 8; ++kb) {
            uint32_t a[4];
            {
                const int base = (kb * 8 + lc) * SA_PITCH + wm * 16 + lg;
                a[0] = sA[base];
                a[1] = sA[base + 8];
                a[2] = sA[base + 4 * SA_PITCH];
                a[3] = sA[base + 8 + 4 * SA_PITCH];
            }
            #pragma unroll
            for (int nt = 0; nt < 4; ++nt) {
                const uint4 b = bp[(kb * 4 + nt) * 32];   // LDS.128
                mma_tf32(acc[nt], a, b.x, b.y);
                mma_tf32(acc[nt], a, b.z, b.w);
            }
        }
        __syncthreads();   // frag + xm reads done; reuse this A buffer as stage

        float* stageT = reinterpret_cast<float*>(sA);   // [o][tv] pitch 132
        {
            const int row = wm * 16 + lg;
            #pragma unroll
            for (int nt = 0; nt < 4; ++nt) {
                const int col = wn * 32 + nt * 8 + 2 * lc;
                const float b0v = sb3[col], b1v = sb3[col + 1];
                stageT[col * ST_PITCH + row]             = acc[nt][0] + b0v;
                stageT[(col + 1) * ST_PITCH + row]       = acc[nt][1] + b1v;
                stageT[col * ST_PITCH + row + 8]         = acc[nt][2] + b0v;
                stageT[(col + 1) * ST_PITCH + row + 8]   = acc[nt][3] + b1v;
            }
        }
        __syncthreads();

        #pragma unroll
        for (int r = 0; r < 4; ++r) {
            const int o = wid * 4 + r;
            const float4 v = *reinterpret_cast<const float4*>(&stageT[o * ST_PITCH + 4 * lane]);
            *reinterpret_cast<float4*>(g_x3 + (size_t)(n * CO_ + o) * TV_ + tv0 + 4 * lane) = v;
        }
        __syncthreads();
    }

    // write per-chunk xm partials
    {
        float* dst = g_xmp + ((size_t)n * NCHUNK + chunk) * (C_ * V_);
        int slot = 0;
        for (int kk = tid; kk < C_ * V_; kk += 512, ++slot) dst[kk] = xmacc[slot];
    }
}

// ---------------------------------------------------------------------------
// Kernel 3b (round-11 proven version): per block (n,o):
//   z[t,u] = sum_v adj[u,v] * x3[t,v]   via 13 f32x2 pairs per u.
// ---------------------------------------------------------------------------
__global__ void __launch_bounds__(256, 5)
k3b_apply(float* __restrict__ z) {
    __shared__ float sadj[V_ * ADJP];        // [u][28], pads zero
    __shared__ float sbuf[T_ * ADJP];        // [t][28] x3 tile -> flat z tile

    const int blk = blockIdx.x;       // n*64 + o
    const int tid = threadIdx.x;      // = t

    const float* asrc = g_adj + (size_t)blk * (V_ * ADJP);
    for (int i = tid; i < V_ * ADJP; i += 256) sadj[i] = asrc[i];

    const float4* xsrc = reinterpret_cast<const float4*>(g_x3 + (size_t)blk * TV_);
    for (int i = tid; i < TV_ / 4; i += 256) {
        const float4 f = xsrc[i];
        const int e = i * 4;
        float fv[4] = {f.x, f.y, f.z, f.w};
        #pragma unroll
        for (int k = 0; k < 4; ++k) {
            const int ee = e + k;
            const int t = ee / 25, v = ee - t * 25;
            sbuf[t * ADJP + v] = fv[k];
        }
    }
    sbuf[tid * ADJP + 25] = 0.f;
    __syncthreads();

    u64 xr2[13];
    {
        const u64* r2 = reinterpret_cast<const u64*>(&sbuf[tid * ADJP]);
        #pragma unroll
        for (int j = 0; j < 13; ++j) xr2[j] = r2[j];
    }
    __syncthreads();

    float* zrow = &sbuf[tid * V_];
    #pragma unroll
    for (int u = 0; u < 25; ++u) {
        const u64* ar = reinterpret_cast<const u64*>(&sadj[u * ADJP]);
        u64 acc = 0ull;
        #pragma unroll
        for (int j = 0; j < 13; ++j) acc = fma2(ar[j], xr2[j], acc);
        float lo, hi; unpack2(acc, lo, hi);
        zrow[u] = lo + hi;
    }
    __syncthreads();

    float4* zb = reinterpret_cast<float4*>(z + (size_t)blk * TV_);
    const float4* s4 = reinterpret_cast<const float4*>(sbuf);
    for (int i = tid; i < TV_ / 4; i += 256) zb[i] = s4[i];
}

// ---------------------------------------------------------------------------
extern "C" void kernel_launch(void* const* d_in, const int* in_sizes, int n_in,
                              void* d_out, int out_size) {
    (void)in_sizes; (void)n_in; (void)out_size;
    const float* x  = (const float*)d_in[0];
    const float* A  = (const float*)d_in[1];
    const float* W1 = (const float*)d_in[2];
    const float* b1 = (const float*)d_in[3];
    const float* W2 = (const float*)d_in[4];
    const float* b2 = (const float*)d_in[5];
    const float* W3 = (const float*)d_in[6];
    const float* b3 = (const float*)d_in[7];
    const float* W4 = (const float*)d_in[8];
    const float* b4 = (const float*)d_in[9];
    float* z = (float*)d_out;

    cudaFuncSetAttribute(k3a_hmma, cudaFuncAttributeMaxDynamicSharedMemorySize, K3A_SMEM);

    k3a_hmma<<<N_ * 10, 512, K3A_SMEM>>>(x, W3, b3);   // also emits xm partials
    k2_adj<<<N_, 256>>>(A, W1, b1, W2, b2, W4, b4);
    k3b_apply<<<N_ * CO_, 256>>>(z);
}